// round 8
// baseline (speedup 1.0000x reference)
#include <cuda_runtime.h>
#include <math.h>

#define BB 64
#define NN 8732
#define CC 21
#define MM 16
#define BN (BB*NN)
#define GRID 112
#define TPB  256
#define STRIDE (GRID*TPB)

// ---- persistent scratch (no allocations allowed) ----
__device__ float        g_vbuf[BN];
__device__ int          g_ktab[BB*MM];
__device__ int          g_ctab[BB*MM];
__device__ unsigned int g_hist1[4096];
__device__ unsigned int g_h2c[4096];
__device__ float        g_h2s[4096];
__device__ double       g_posCe;     // reset at end of each execution
__device__ double       g_negHi;     // "
__device__ double       g_bboxSum;   // "
__device__ int          g_posCnt;    // "
__device__ int          g_validCnt;  // "
__device__ int          g_b0;
__device__ int          g_cntAbove1;
__device__ unsigned int g_c0, g_c1, g_c2;          // barrier arrival ctrs (reset at end)
__device__ volatile unsigned int g_f0, g_f1;       // barrier release flags (reset at end)

__device__ __forceinline__ float smooth_l1(float d) {
    float a = fabsf(d);
    return a < 1.0f ? 0.5f * d * d : a - 0.5f;
}

__global__ void __launch_bounds__(TPB) k_fused(const float* __restrict__ conf,
                                               const float* __restrict__ bboxOut,
                                               const float* __restrict__ target,
                                               const float* __restrict__ predBoxes,
                                               float* __restrict__ out) {
    __shared__ unsigned int sh[4096];
    __shared__ int sk[BB*MM];
    __shared__ int sc[BB*MM];
    __shared__ unsigned int ssum[256];
    __shared__ double sred[256];
    __shared__ bool sLast;

    const int tid = threadIdx.x;
    const int bid = blockIdx.x;
    const int gid = bid * TPB + tid;

    // ================= Phase 0: zero hist arrays + parse targets =================
    // NOTE: scalar accumulators (g_posCe, g_bboxSum, counts, barrier state) were
    // reset by the finalizing block of the PREVIOUS execution (zero-init on first).
    if (gid < 4096) {
        g_hist1[gid] = 0u;
        g_h2c[gid]   = 0u;
        g_h2s[gid]   = 0.0f;
    }

    // parse: block b (0..63), warp 0, lanes 0..15 handle the 16 entries of batch b
    if (bid < BB && tid < 32) {
        bool valid = false, pos = false;
        double s = 0.0;
        if (tid < MM) {
            int m = tid;
            const float* t = target + bid * (1 + 6 * MM);
            int num = (int)t[0];
            const float* e = t + 1 + 6 * m;
            int ci = (int)e[0];
            int k  = (int)e[5];
            valid = (m < num);
            g_ktab[bid * MM + m] = valid ? k : -1;
            g_ctab[bid * MM + m] = (valid && ci > 0) ? ci : 0;
            if (valid) {
                pos = (ci > 0);
                float tx1 = e[1], ty1 = e[2], tx2 = e[3], ty2 = e[4];
                const float* p = predBoxes + (size_t)k * 4;
                float px1 = p[0], py1 = p[1], px2 = p[2], py2 = p[3];
                float pw = px2 - px1, ph = py2 - py1;
                float eb0 = ((tx1 + tx2) * 0.5f - (px1 + px2) * 0.5f) / pw;
                float eb1 = ((ty1 + ty2) * 0.5f - (py1 + py2) * 0.5f) / ph;
                float eb2 = logf((tx2 - tx1) / pw);
                float eb3 = logf((ty2 - ty1) / ph);
                const float* bo = bboxOut + ((size_t)bid * NN + (size_t)k) * 4;
                s = (double)(smooth_l1(bo[0] - eb0) + smooth_l1(bo[1] - eb1)
                           + smooth_l1(bo[2] - eb2) + smooth_l1(bo[3] - eb3));
            }
        }
        unsigned vmask = __ballot_sync(0xFFFFFFFFu, valid);
        unsigned pmask = __ballot_sync(0xFFFFFFFFu, pos);
#pragma unroll
        for (int off = 16; off > 0; off >>= 1)
            s += __shfl_down_sync(0xFFFFFFFFu, s, off);
        if (tid == 0) {
            atomicAdd(&g_validCnt, (int)__popc(vmask));
            atomicAdd(&g_posCnt,   (int)__popc(pmask));
            atomicAdd(&g_bboxSum,  s);
        }
    }

    // zero block-local hist + preload assignment tables (used after bar0)
    for (int i = tid; i < 4096; i += TPB) sh[i] = 0u;

    // ---- bar0: phase-0 global writes visible grid-wide ----
    __threadfence();
    __syncthreads();
    if (tid == 0) {
        if (atomicAdd(&g_c0, 1u) == GRID - 1) { __threadfence(); g_f0 = 1u; }
        else { while (g_f0 == 0u) __nanosleep(64); }
        __threadfence();
    }
    __syncthreads();

    // load full ktab/ctab into shared (after bar0: parse complete grid-wide)
    for (int i = tid; i < BB * MM; i += TPB) { sk[i] = g_ktab[i]; sc[i] = g_ctab[i]; }
    __syncthreads();

    // ================= Phase 1: log-softmax, pos CE, vbuf + level-1 hist ========
    for (int i = gid; i < BN; i += STRIDE) {
        int b = i / NN;
        int n = i - b * NN;
        const float* row = conf + (size_t)i * CC;
        float r[CC];
#pragma unroll
        for (int c = 0; c < CC; c++) r[c] = __ldg(row + c);
        float mx = r[0];
#pragma unroll
        for (int c = 1; c < CC; c++) mx = fmaxf(mx, r[c]);
        float se = 0.0f;
#pragma unroll
        for (int c = 0; c < CC; c++) se += __expf(r[c] - mx);
        float logZ = mx + __logf(se);

        int cls = -1;
        const int base = b << 4;
#pragma unroll
        for (int m = 0; m < MM; m++)
            if (sk[base + m] == n) cls = sc[base + m];

        if (cls < 0) {
            float v = fmaxf(logZ - r[0], 0.0f);
            g_vbuf[i] = v;
            atomicAdd(&sh[__float_as_uint(v) >> 20], 1u);
        } else {
            g_vbuf[i] = 0.0f;
            if (cls > 0) atomicAdd(&g_posCe, (double)(logZ - r[cls]));
        }
    }
    __syncthreads();
    for (int i = tid; i < 4096; i += TPB) {
        unsigned int c = sh[i];
        if (c) atomicAdd(&g_hist1[i], c);
    }

    // ---- bar1: last block scans level-1 hist, publishes b0 ----
    __threadfence();
    __syncthreads();
    if (tid == 0) sLast = (atomicAdd(&g_c1, 1u) == GRID - 1);
    __syncthreads();
    if (sLast) {
        unsigned int c[16];
        unsigned int s = 0;
#pragma unroll
        for (int j = 0; j < 16; j++) { c[j] = __ldcg(&g_hist1[tid * 16 + j]); s += c[j]; }
        ssum[tid] = s;
        __syncthreads();
        for (int off = 1; off < 256; off <<= 1) {
            unsigned int v = (tid + off < 256) ? ssum[tid + off] : 0u;
            __syncthreads();
            ssum[tid] += v;
            __syncthreads();
        }
        int K = 3 * g_posCnt;
        unsigned int e = (tid < 255) ? ssum[tid + 1] : 0u;
#pragma unroll
        for (int j = 15; j >= 0; j--) {
            if ((int)e < K && (int)(e + c[j]) >= K) { g_b0 = tid * 16 + j; g_cntAbove1 = (int)e; }
            e += c[j];
        }
        if (tid == 0 && (int)ssum[0] < K) { g_b0 = 0; g_cntAbove1 = (int)ssum[0]; }
        __threadfence();
        __syncthreads();
        if (tid == 0) g_f1 = 1u;
    }
    if (tid == 0) { while (g_f1 == 0u) __nanosleep(64); __threadfence(); }
    __syncthreads();

    // ================= Phase 2: sum above boundary + level-2 hist ===============
    const int b0 = g_b0;
    for (int i = gid; i < BN; i += STRIDE) {
        float v = g_vbuf[i];
        unsigned int bits = __float_as_uint(v);
        if (bits == 0u) continue;
        int t12 = (int)(bits >> 20);
        if (t12 > b0) {
            atomicAdd(&g_negHi, (double)v);
        } else if (t12 == b0) {
            unsigned int b2 = (bits >> 8) & 0xFFFu;
            atomicAdd(&g_h2c[b2], 1u);
            atomicAdd(&g_h2s[b2], v);
        }
    }

    // ---- final arrival: last block finalizes, resets state, writes out ----
    __threadfence();
    __syncthreads();
    if (tid == 0) sLast = (atomicAdd(&g_c2, 1u) == GRID - 1);
    __syncthreads();
    if (!sLast) return;

    {
        unsigned int c[16];
        float        bs[16];
        unsigned int s = 0;
#pragma unroll
        for (int j = 0; j < 16; j++) {
            c[j]  = __ldcg(&g_h2c[tid * 16 + j]);
            bs[j] = __ldcg(&g_h2s[tid * 16 + j]);
            s += c[j];
        }
        ssum[tid] = s;
        __syncthreads();
        for (int off = 1; off < 256; off <<= 1) {
            unsigned int v = (tid + off < 256) ? ssum[tid + off] : 0u;
            __syncthreads();
            ssum[tid] += v;
            __syncthreads();
        }

        int K = 3 * g_posCnt;
        long long r = (long long)K - (long long)g_cntAbove1;
        if (r < 0) r = 0;

        unsigned int e = (tid < 255) ? ssum[tid + 1] : 0u;
        double local = 0.0;
#pragma unroll
        for (int j = 15; j >= 0; j--) {
            unsigned int cj = c[j];
            if (cj) {
                long long rem = r - (long long)e;
                long long take = rem < 0 ? 0 : (rem > (long long)cj ? (long long)cj : rem);
                if (take > 0)
                    local += (double)bs[j] * ((double)take / (double)cj);
            }
            e += cj;
        }
        sred[tid] = local;
        __syncthreads();
        for (int off = 128; off > 0; off >>= 1) {
            if (tid < off) sred[tid] += sred[tid + off];
            __syncthreads();
        }

        if (tid == 0) {
            // read everything into locals BEFORE resetting
            double posCe   = __ldcg(&g_posCe);
            double negHi   = __ldcg(&g_negHi);
            double bboxSum = __ldcg(&g_bboxSum);
            int    posCnt  = g_posCnt;
            int    validCnt= g_validCnt;

            double sneg = negHi + sred[0];
            long long selCnt = (long long)posCnt + (long long)(3 * posCnt);
            if (selCnt < 1) selCnt = 1;
            double conf_loss = (posCe + sneg) / (double)selCnt;
            long long denomB = 4LL * (long long)validCnt;
            if (denomB < 1) denomB = 1;
            double bbox_loss = bboxSum / (double)denomB;

            // reset persistent state for the next execution (graph replay)
            g_c0 = 0u; g_c1 = 0u; g_c2 = 0u; g_f0 = 0u; g_f1 = 0u;
            g_posCe = 0.0; g_negHi = 0.0; g_bboxSum = 0.0;
            g_posCnt = 0;  g_validCnt = 0;

            out[0] = (float)conf_loss;
            out[1] = (float)bbox_loss;
        }
    }
}

extern "C" void kernel_launch(void* const* d_in, const int* in_sizes, int n_in,
                              void* d_out, int out_size) {
    const float* conf   = (const float*)d_in[0];   // (B, N, C)
    const float* bbox   = (const float*)d_in[1];   // (B, N, 4)
    const float* target = (const float*)d_in[2];   // (B, 1+6M)
    const float* pred   = (const float*)d_in[3];   // (N, 4)
    float* out = (float*)d_out;

    k_fused<<<GRID, TPB>>>(conf, bbox, target, pred, out);
}

// round 11
// speedup vs baseline: 1.1997x; 1.1997x over previous
#include <cuda_runtime.h>
#include <math.h>

#define BB 64
#define NN 8732
#define CC 21
#define MM 16
#define BN (BB*NN)
#define GRID 296                 // 148 SMs x 2 blocks; compiler constrained for 4/SM
#define TPB  256
#define STRIDE (GRID*TPB)

// ---- persistent scratch (no allocations allowed) ----
__device__ float        g_vbuf[BN];
__device__ int          g_ktab[BB*MM];
__device__ int          g_ctab[BB*MM];
__device__ unsigned int g_hist1[4096];
__device__ unsigned int g_h2c[4096];
__device__ float        g_h2s[4096];
__device__ double       g_posCe;     // reset at end of each execution
__device__ double       g_negHi;     // "
__device__ double       g_bboxSum;   // "
__device__ int          g_posCnt;    // "
__device__ int          g_validCnt;  // "
__device__ int          g_b0;
__device__ int          g_cntAbove1;
__device__ unsigned int g_c0, g_c1, g_c2;          // barrier arrival ctrs (reset at end)
__device__ volatile unsigned int g_f0, g_f1;       // barrier release flags (reset at end)

__device__ __forceinline__ float smooth_l1(float d) {
    float a = fabsf(d);
    return a < 1.0f ? 0.5f * d * d : a - 0.5f;
}

__global__ void __launch_bounds__(TPB, 4) k_fused(const float* __restrict__ conf,
                                                  const float* __restrict__ bboxOut,
                                                  const float* __restrict__ target,
                                                  const float* __restrict__ predBoxes,
                                                  float* __restrict__ out) {
    __shared__ unsigned int sh[4096];
    __shared__ int sk[BB*MM];
    __shared__ int sc[BB*MM];
    __shared__ unsigned int ssum[256];
    __shared__ double sred[256];
    __shared__ bool sLast;

    const int tid = threadIdx.x;
    const int bid = blockIdx.x;
    const int gid = bid * TPB + tid;

    // ================= Phase 0: zero hist arrays + parse targets =================
    // Scalar accumulators/barrier state were reset by the finalizing block of the
    // PREVIOUS execution (globals zero-init on the very first run).
    if (gid < 4096) {
        g_hist1[gid] = 0u;
        g_h2c[gid]   = 0u;
        g_h2s[gid]   = 0.0f;
    }

    // parse: block b (0..63), warp 0, lanes 0..15 handle the 16 entries of batch b
    if (bid < BB && tid < 32) {
        bool valid = false, pos = false;
        double s = 0.0;
        if (tid < MM) {
            int m = tid;
            const float* t = target + bid * (1 + 6 * MM);
            int num = (int)t[0];
            const float* e = t + 1 + 6 * m;
            int ci = (int)e[0];
            int k  = (int)e[5];
            valid = (m < num);
            g_ktab[bid * MM + m] = valid ? k : -1;
            g_ctab[bid * MM + m] = (valid && ci > 0) ? ci : 0;
            if (valid) {
                pos = (ci > 0);
                float tx1 = e[1], ty1 = e[2], tx2 = e[3], ty2 = e[4];
                const float* p = predBoxes + (size_t)k * 4;
                float px1 = p[0], py1 = p[1], px2 = p[2], py2 = p[3];
                float pw = px2 - px1, ph = py2 - py1;
                float eb0 = ((tx1 + tx2) * 0.5f - (px1 + px2) * 0.5f) / pw;
                float eb1 = ((ty1 + ty2) * 0.5f - (py1 + py2) * 0.5f) / ph;
                float eb2 = logf((tx2 - tx1) / pw);
                float eb3 = logf((ty2 - ty1) / ph);
                const float* bo = bboxOut + ((size_t)bid * NN + (size_t)k) * 4;
                s = (double)(smooth_l1(bo[0] - eb0) + smooth_l1(bo[1] - eb1)
                           + smooth_l1(bo[2] - eb2) + smooth_l1(bo[3] - eb3));
            }
        }
        unsigned vmask = __ballot_sync(0xFFFFFFFFu, valid);
        unsigned pmask = __ballot_sync(0xFFFFFFFFu, pos);
#pragma unroll
        for (int off = 16; off > 0; off >>= 1)
            s += __shfl_down_sync(0xFFFFFFFFu, s, off);
        if (tid == 0) {
            atomicAdd(&g_validCnt, (int)__popc(vmask));
            atomicAdd(&g_posCnt,   (int)__popc(pmask));
            atomicAdd(&g_bboxSum,  s);
        }
    }

    // zero block-local hist
    for (int i = tid; i < 4096; i += TPB) sh[i] = 0u;

    // ---- bar0: phase-0 global writes visible grid-wide ----
    __threadfence();
    __syncthreads();
    if (tid == 0) {
        if (atomicAdd(&g_c0, 1u) == GRID - 1) { __threadfence(); g_f0 = 1u; }
        else { while (g_f0 == 0u) __nanosleep(64); }
        __threadfence();
    }
    __syncthreads();

    // load full ktab/ctab into shared (after bar0: parse complete grid-wide)
    for (int i = tid; i < BB * MM; i += TPB) { sk[i] = g_ktab[i]; sc[i] = g_ctab[i]; }
    __syncthreads();

    // ================= Phase 1: log-softmax, pos CE, vbuf + level-1 hist ========
    for (int i = gid; i < BN; i += STRIDE) {
        int b = i / NN;
        int n = i - b * NN;
        const float* row = conf + (size_t)i * CC;
        float r[CC];
#pragma unroll
        for (int c = 0; c < CC; c++) r[c] = __ldg(row + c);
        float mx = r[0];
#pragma unroll
        for (int c = 1; c < CC; c++) mx = fmaxf(mx, r[c]);
        float se = 0.0f;
#pragma unroll
        for (int c = 0; c < CC; c++) se += __expf(r[c] - mx);
        float logZ = mx + __logf(se);

        int cls = -1;
        const int base = b << 4;
#pragma unroll
        for (int m = 0; m < MM; m++)
            if (sk[base + m] == n) cls = sc[base + m];

        if (cls < 0) {
            float v = fmaxf(logZ - r[0], 0.0f);
            g_vbuf[i] = v;
            atomicAdd(&sh[__float_as_uint(v) >> 20], 1u);
        } else {
            g_vbuf[i] = 0.0f;
            if (cls > 0) atomicAdd(&g_posCe, (double)(logZ - r[cls]));
        }
    }
    __syncthreads();
    for (int i = tid; i < 4096; i += TPB) {
        unsigned int c = sh[i];
        if (c) atomicAdd(&g_hist1[i], c);
    }

    // ---- bar1: last block scans level-1 hist, publishes b0 ----
    __threadfence();
    __syncthreads();
    if (tid == 0) sLast = (atomicAdd(&g_c1, 1u) == GRID - 1);
    __syncthreads();
    if (sLast) {
        unsigned int c[16];
        unsigned int s = 0;
#pragma unroll
        for (int j = 0; j < 16; j++) { c[j] = __ldcg(&g_hist1[tid * 16 + j]); s += c[j]; }
        ssum[tid] = s;
        __syncthreads();
        for (int off = 1; off < 256; off <<= 1) {
            unsigned int v = (tid + off < 256) ? ssum[tid + off] : 0u;
            __syncthreads();
            ssum[tid] += v;
            __syncthreads();
        }
        int K = 3 * g_posCnt;
        unsigned int e = (tid < 255) ? ssum[tid + 1] : 0u;
#pragma unroll
        for (int j = 15; j >= 0; j--) {
            if ((int)e < K && (int)(e + c[j]) >= K) { g_b0 = tid * 16 + j; g_cntAbove1 = (int)e; }
            e += c[j];
        }
        if (tid == 0 && (int)ssum[0] < K) { g_b0 = 0; g_cntAbove1 = (int)ssum[0]; }
        __threadfence();
        __syncthreads();
        if (tid == 0) g_f1 = 1u;
    }
    if (tid == 0) { while (g_f1 == 0u) __nanosleep(64); __threadfence(); }
    __syncthreads();

    // ================= Phase 2: sum above boundary + level-2 hist ===============
    const int b0 = g_b0;
    for (int i = gid; i < BN; i += STRIDE) {
        float v = g_vbuf[i];
        unsigned int bits = __float_as_uint(v);
        if (bits == 0u) continue;
        int t12 = (int)(bits >> 20);
        if (t12 > b0) {
            atomicAdd(&g_negHi, (double)v);
        } else if (t12 == b0) {
            unsigned int b2 = (bits >> 8) & 0xFFFu;
            atomicAdd(&g_h2c[b2], 1u);
            atomicAdd(&g_h2s[b2], v);
        }
    }

    // ---- final arrival: last block finalizes, resets state, writes out ----
    __threadfence();
    __syncthreads();
    if (tid == 0) sLast = (atomicAdd(&g_c2, 1u) == GRID - 1);
    __syncthreads();
    if (!sLast) return;

    {
        unsigned int c[16];
        float        bs[16];
        unsigned int s = 0;
#pragma unroll
        for (int j = 0; j < 16; j++) {
            c[j]  = __ldcg(&g_h2c[tid * 16 + j]);
            bs[j] = __ldcg(&g_h2s[tid * 16 + j]);
            s += c[j];
        }
        ssum[tid] = s;
        __syncthreads();
        for (int off = 1; off < 256; off <<= 1) {
            unsigned int v = (tid + off < 256) ? ssum[tid + off] : 0u;
            __syncthreads();
            ssum[tid] += v;
            __syncthreads();
        }

        int K = 3 * g_posCnt;
        long long r = (long long)K - (long long)g_cntAbove1;
        if (r < 0) r = 0;

        unsigned int e = (tid < 255) ? ssum[tid + 1] : 0u;
        double local = 0.0;
#pragma unroll
        for (int j = 15; j >= 0; j--) {
            unsigned int cj = c[j];
            if (cj) {
                long long rem = r - (long long)e;
                long long take = rem < 0 ? 0 : (rem > (long long)cj ? (long long)cj : rem);
                if (take > 0)
                    local += (double)bs[j] * ((double)take / (double)cj);
            }
            e += cj;
        }
        sred[tid] = local;
        __syncthreads();
        for (int off = 128; off > 0; off >>= 1) {
            if (tid < off) sred[tid] += sred[tid + off];
            __syncthreads();
        }

        if (tid == 0) {
            // read everything into locals BEFORE resetting
            double posCe    = __ldcg(&g_posCe);
            double negHi    = __ldcg(&g_negHi);
            double bboxSum  = __ldcg(&g_bboxSum);
            int    posCnt   = g_posCnt;
            int    validCnt = g_validCnt;

            double sneg = negHi + sred[0];
            long long selCnt = (long long)posCnt + (long long)(3 * posCnt);
            if (selCnt < 1) selCnt = 1;
            double conf_loss = (posCe + sneg) / (double)selCnt;
            long long denomB = 4LL * (long long)validCnt;
            if (denomB < 1) denomB = 1;
            double bbox_loss = bboxSum / (double)denomB;

            // reset persistent state for the next execution (graph replay)
            g_c0 = 0u; g_c1 = 0u; g_c2 = 0u; g_f0 = 0u; g_f1 = 0u;
            g_posCe = 0.0; g_negHi = 0.0; g_bboxSum = 0.0;
            g_posCnt = 0;  g_validCnt = 0;

            out[0] = (float)conf_loss;
            out[1] = (float)bbox_loss;
        }
    }
}

extern "C" void kernel_launch(void* const* d_in, const int* in_sizes, int n_in,
                              void* d_out, int out_size) {
    const float* conf   = (const float*)d_in[0];   // (B, N, C)
    const float* bbox   = (const float*)d_in[1];   // (B, N, 4)
    const float* target = (const float*)d_in[2];   // (B, 1+6M)
    const float* pred   = (const float*)d_in[3];   // (N, 4)
    float* out = (float*)d_out;

    k_fused<<<GRID, TPB>>>(conf, bbox, target, pred, out);
}

// round 14
// speedup vs baseline: 1.2767x; 1.0642x over previous
#include <cuda_runtime.h>
#include <math.h>

#define BB 64
#define NN 8732
#define CC 21
#define MM 16
#define BN (BB*NN)
#define GRID 296                 // 148 SMs x 2 blocks (proven-safe residency)
#define TPB  256
#define TILE 256                 // anchors per tile; BN = 2183 * 256 exactly
#define NTILES (BN/TILE)
#define TILE_F (TILE*CC)         // 5376 floats
#define TILE_V4 (TILE_F/4)       // 1344 float4

// ---- persistent scratch (no allocations allowed) ----
__device__ float        g_vbuf[BN];
__device__ int          g_ptab[BB*MM];     // packed (k<<8)|cls, or 0x80000000 invalid
__device__ unsigned int g_hist1[4096];
__device__ unsigned int g_h2c[4096];
__device__ float        g_h2s[4096];
__device__ double       g_posCe;     // reset at end of each execution
__device__ double       g_negHi;     // "
__device__ double       g_bboxSum;   // "
__device__ int          g_posCnt;    // "
__device__ int          g_validCnt;  // "
__device__ int          g_b0;
__device__ int          g_cntAbove1;
__device__ unsigned int g_c0, g_c1, g_c2;          // barrier arrival ctrs (reset at end)
__device__ volatile unsigned int g_f0, g_f1;       // barrier release flags (reset at end)

__device__ __forceinline__ float smooth_l1(float d) {
    float a = fabsf(d);
    return a < 1.0f ? 0.5f * d * d : a - 0.5f;
}

__global__ void __launch_bounds__(TPB, 4) k_fused(const float* __restrict__ conf,
                                                  const float* __restrict__ bboxOut,
                                                  const float* __restrict__ target,
                                                  const float* __restrict__ predBoxes,
                                                  float* __restrict__ out) {
    // static smem budget (48 KB limit): 21504 + 16384 + 4096 + 1024 + 2048 + 8 = 45064
    __shared__ float        st[TILE_F];    // coalesced conf tile (21504 B)
    __shared__ unsigned int sh[4096];      // level-1 histogram   (16384 B)
    __shared__ int          spk[BB*MM];    // packed (k<<8)|cls    (4096 B)
    __shared__ unsigned int ssum[256];     //                      (1024 B)
    __shared__ double       sred[256];     //                      (2048 B)
    __shared__ bool sLast;

    const int tid = threadIdx.x;
    const int bid = blockIdx.x;
    const int gid = bid * TPB + tid;

    // ================= Phase 0: zero hist arrays + parse targets =================
    // Scalar accumulators/barrier state were reset by the finalizing block of the
    // PREVIOUS execution (globals zero-init on the very first run).
    if (gid < 4096) {
        g_hist1[gid] = 0u;
        g_h2c[gid]   = 0u;
        g_h2s[gid]   = 0.0f;
    }

    // parse: block b (0..63), warp 0, lanes 0..15 handle the 16 entries of batch b
    if (bid < BB && tid < 32) {
        bool valid = false, pos = false;
        double s = 0.0;
        if (tid < MM) {
            int m = tid;
            const float* t = target + bid * (1 + 6 * MM);
            int num = (int)t[0];
            const float* e = t + 1 + 6 * m;
            int ci = (int)e[0];
            int k  = (int)e[5];
            valid = (m < num);
            int cls = (valid && ci > 0) ? ci : 0;
            g_ptab[bid * MM + m] = valid ? ((k << 8) | cls) : (int)0x80000000;
            if (valid) {
                pos = (ci > 0);
                float tx1 = e[1], ty1 = e[2], tx2 = e[3], ty2 = e[4];
                const float* p = predBoxes + (size_t)k * 4;
                float px1 = p[0], py1 = p[1], px2 = p[2], py2 = p[3];
                float pw = px2 - px1, ph = py2 - py1;
                float eb0 = ((tx1 + tx2) * 0.5f - (px1 + px2) * 0.5f) / pw;
                float eb1 = ((ty1 + ty2) * 0.5f - (py1 + py2) * 0.5f) / ph;
                float eb2 = logf((tx2 - tx1) / pw);
                float eb3 = logf((ty2 - ty1) / ph);
                const float* bo = bboxOut + ((size_t)bid * NN + (size_t)k) * 4;
                s = (double)(smooth_l1(bo[0] - eb0) + smooth_l1(bo[1] - eb1)
                           + smooth_l1(bo[2] - eb2) + smooth_l1(bo[3] - eb3));
            }
        }
        unsigned vmask = __ballot_sync(0xFFFFFFFFu, valid);
        unsigned pmask = __ballot_sync(0xFFFFFFFFu, pos);
#pragma unroll
        for (int off = 16; off > 0; off >>= 1)
            s += __shfl_down_sync(0xFFFFFFFFu, s, off);
        if (tid == 0) {
            atomicAdd(&g_validCnt, (int)__popc(vmask));
            atomicAdd(&g_posCnt,   (int)__popc(pmask));
            atomicAdd(&g_bboxSum,  s);
        }
    }

    // zero block-local hist
    for (int i = tid; i < 4096; i += TPB) sh[i] = 0u;

    // ---- bar0: phase-0 global writes visible grid-wide ----
    __threadfence();
    __syncthreads();
    if (tid == 0) {
        if (atomicAdd(&g_c0, 1u) == GRID - 1) { __threadfence(); g_f0 = 1u; }
        else { while (g_f0 == 0u) __nanosleep(64); }
        __threadfence();
    }
    __syncthreads();

    // load packed assignment table into shared (after bar0: parse complete)
    for (int i = tid; i < BB * MM; i += TPB) spk[i] = g_ptab[i];

    // ================= Phase 1: tiled, coalesced log-softmax ====================
    for (int t = bid; t < NTILES; t += GRID) {
        __syncthreads();   // previous tile fully consumed (also covers spk load)
        const float4* src = (const float4*)(conf + (size_t)t * TILE_F);
#pragma unroll
        for (int i = tid; i < TILE_V4; i += TPB)
            ((float4*)st)[i] = src[i];
        __syncthreads();

        const int i = t * TILE + tid;          // global anchor index (one per thread)
        const int b = i / NN;
        const int n = i - b * NN;
        const float* row = st + tid * CC;      // stride 21: bank-conflict-free

        float r[CC];
#pragma unroll
        for (int c = 0; c < CC; c++) r[c] = row[c];
        float mx = r[0];
#pragma unroll
        for (int c = 1; c < CC; c++) mx = fmaxf(mx, r[c]);
        float se = 0.0f;
#pragma unroll
        for (int c = 0; c < CC; c++) se += __expf(r[c] - mx);
        float logZ = mx + __logf(se);

        int cls = -1;
        const int base = b << 4;
#pragma unroll
        for (int m = 0; m < MM; m++) {
            int p = spk[base + m];
            if ((p >> 8) == n) cls = p & 0xFF;   // invalid: p>>8 negative, never == n
        }

        if (cls < 0) {
            float v = fmaxf(logZ - r[0], 0.0f);
            g_vbuf[i] = v;
            atomicAdd(&sh[__float_as_uint(v) >> 20], 1u);
        } else {
            g_vbuf[i] = 0.0f;
            if (cls > 0) atomicAdd(&g_posCe, (double)(logZ - r[cls]));
        }
    }
    __syncthreads();
    for (int i = tid; i < 4096; i += TPB) {
        unsigned int c = sh[i];
        if (c) atomicAdd(&g_hist1[i], c);
    }

    // ---- bar1: last block scans level-1 hist, publishes b0 ----
    __threadfence();
    __syncthreads();
    if (tid == 0) sLast = (atomicAdd(&g_c1, 1u) == GRID - 1);
    __syncthreads();
    if (sLast) {
        unsigned int c[16];
        unsigned int s = 0;
#pragma unroll
        for (int j = 0; j < 16; j++) { c[j] = __ldcg(&g_hist1[tid * 16 + j]); s += c[j]; }
        ssum[tid] = s;
        __syncthreads();
        for (int off = 1; off < 256; off <<= 1) {
            unsigned int v = (tid + off < 256) ? ssum[tid + off] : 0u;
            __syncthreads();
            ssum[tid] += v;
            __syncthreads();
        }
        int K = 3 * g_posCnt;
        unsigned int e = (tid < 255) ? ssum[tid + 1] : 0u;
#pragma unroll
        for (int j = 15; j >= 0; j--) {
            if ((int)e < K && (int)(e + c[j]) >= K) { g_b0 = tid * 16 + j; g_cntAbove1 = (int)e; }
            e += c[j];
        }
        if (tid == 0 && (int)ssum[0] < K) { g_b0 = 0; g_cntAbove1 = (int)ssum[0]; }
        __threadfence();
        __syncthreads();
        if (tid == 0) g_f1 = 1u;
    }
    if (tid == 0) { while (g_f1 == 0u) __nanosleep(64); __threadfence(); }
    __syncthreads();

    // ================= Phase 2: sum above boundary + level-2 hist ===============
    const int b0 = g_b0;
    for (int i = gid; i < BN; i += GRID * TPB) {
        float v = g_vbuf[i];
        unsigned int bits = __float_as_uint(v);
        if (bits == 0u) continue;
        int t12 = (int)(bits >> 20);
        if (t12 > b0) {
            atomicAdd(&g_negHi, (double)v);
        } else if (t12 == b0) {
            unsigned int b2 = (bits >> 8) & 0xFFFu;
            atomicAdd(&g_h2c[b2], 1u);
            atomicAdd(&g_h2s[b2], v);
        }
    }

    // ---- final arrival: last block finalizes, resets state, writes out ----
    __threadfence();
    __syncthreads();
    if (tid == 0) sLast = (atomicAdd(&g_c2, 1u) == GRID - 1);
    __syncthreads();
    if (!sLast) return;

    {
        unsigned int c[16];
        float        bs[16];
        unsigned int s = 0;
#pragma unroll
        for (int j = 0; j < 16; j++) {
            c[j]  = __ldcg(&g_h2c[tid * 16 + j]);
            bs[j] = __ldcg(&g_h2s[tid * 16 + j]);
            s += c[j];
        }
        ssum[tid] = s;
        __syncthreads();
        for (int off = 1; off < 256; off <<= 1) {
            unsigned int v = (tid + off < 256) ? ssum[tid + off] : 0u;
            __syncthreads();
            ssum[tid] += v;
            __syncthreads();
        }

        int K = 3 * g_posCnt;
        long long r = (long long)K - (long long)g_cntAbove1;
        if (r < 0) r = 0;

        unsigned int e = (tid < 255) ? ssum[tid + 1] : 0u;
        double local = 0.0;
#pragma unroll
        for (int j = 15; j >= 0; j--) {
            unsigned int cj = c[j];
            if (cj) {
                long long rem = r - (long long)e;
                long long take = rem < 0 ? 0 : (rem > (long long)cj ? (long long)cj : rem);
                if (take > 0)
                    local += (double)bs[j] * ((double)take / (double)cj);
            }
            e += cj;
        }
        sred[tid] = local;
        __syncthreads();
        for (int off = 128; off > 0; off >>= 1) {
            if (tid < off) sred[tid] += sred[tid + off];
            __syncthreads();
        }

        if (tid == 0) {
            // read everything into locals BEFORE resetting
            double posCe    = __ldcg(&g_posCe);
            double negHi    = __ldcg(&g_negHi);
            double bboxSum  = __ldcg(&g_bboxSum);
            int    posCnt   = g_posCnt;
            int    validCnt = g_validCnt;

            double sneg = negHi + sred[0];
            long long selCnt = (long long)posCnt + (long long)(3 * posCnt);
            if (selCnt < 1) selCnt = 1;
            double conf_loss = (posCe + sneg) / (double)selCnt;
            long long denomB = 4LL * (long long)validCnt;
            if (denomB < 1) denomB = 1;
            double bbox_loss = bboxSum / (double)denomB;

            // reset persistent state for the next execution (graph replay)
            g_c0 = 0u; g_c1 = 0u; g_c2 = 0u; g_f0 = 0u; g_f1 = 0u;
            g_posCe = 0.0; g_negHi = 0.0; g_bboxSum = 0.0;
            g_posCnt = 0;  g_validCnt = 0;

            out[0] = (float)conf_loss;
            out[1] = (float)bbox_loss;
        }
    }
}

extern "C" void kernel_launch(void* const* d_in, const int* in_sizes, int n_in,
                              void* d_out, int out_size) {
    const float* conf   = (const float*)d_in[0];   // (B, N, C)
    const float* bbox   = (const float*)d_in[1];   // (B, N, 4)
    const float* target = (const float*)d_in[2];   // (B, 1+6M)
    const float* pred   = (const float*)d_in[3];   // (N, 4)
    float* out = (float*)d_out;

    k_fused<<<GRID, TPB>>>(conf, bbox, target, pred, out);
}